// round 6
// baseline (speedup 1.0000x reference)
#include <cuda_runtime.h>

// Problem shape (fixed by dataset)
#define BB 8
#define DD 8
#define HH 512
#define WW 1024
#define KK 5
#define PP (HH * WW)            // 524288 pixels per image
#define PV (PP / 4)             // 131072 float4/int4 quads per image
#define CHUNKS 64
#define TPB 256
#define ITERS (PV / (CHUNKS * TPB))   // 8 iterations per thread

#define DELTA_V 0.5f
#define DELTA_D 3.0f
#define GAMMA_W 0.001f

// Scratch (no allocations allowed -> __device__ globals)
__device__ float g_sums[BB * KK * DD];   // segment sums
__device__ float g_counts[BB * KK];      // segment counts
__device__ float g_var[BB];              // per-image sum of val/count[label]

// ---------------------------------------------------------------------------
// Kernel 0: zero accumulators
// ---------------------------------------------------------------------------
__global__ void k_zero() {
    int i = threadIdx.x;
    if (i < BB * KK * DD) g_sums[i] = 0.f;
    if (i < BB * KK) g_counts[i] = 0.f;
    if (i < BB) g_var[i] = 0.f;
}

__device__ __forceinline__ float warp_sum(float v) {
    #pragma unroll
    for (int o = 16; o > 0; o >>= 1) v += __shfl_down_sync(0xffffffffu, v, o);
    return v;
}

// ---------------------------------------------------------------------------
// Kernel 1: segment sums + counts, split over d (blockIdx.z picks 4 planes)
// grid: (CHUNKS, B, 2), block 256.  Ascending chunk order (pass2 reverses).
// ---------------------------------------------------------------------------
__global__ void __launch_bounds__(TPB) k_pass1(const float4* __restrict__ emb,
                                               const int4* __restrict__ mask) {
    const int b = blockIdx.y;
    const int z = blockIdx.z;                 // d-half: planes [4z, 4z+4)
    const float4* __restrict__ eb = emb + ((size_t)b * DD + (size_t)z * 4) * PV;
    const int4* __restrict__ mb = mask + (size_t)b * PV;

    float s[KK * 4];
    float cnt[KK];
    #pragma unroll
    for (int i = 0; i < KK * 4; i++) s[i] = 0.f;
    #pragma unroll
    for (int k = 0; k < KK; k++) cnt[k] = 0.f;

    const int base = blockIdx.x * TPB + threadIdx.x;
    #pragma unroll 2
    for (int it = 0; it < ITERS; ++it) {
        const int i = base + it * (CHUNKS * TPB);
        int4 mm = mb[i];
        float w0[KK], w1[KK], w2[KK], w3[KK];
        #pragma unroll
        for (int k = 0; k < KK; k++) {
            w0[k] = (mm.x == k + 1) ? 1.f : 0.f;
            w1[k] = (mm.y == k + 1) ? 1.f : 0.f;
            w2[k] = (mm.z == k + 1) ? 1.f : 0.f;
            w3[k] = (mm.w == k + 1) ? 1.f : 0.f;
            cnt[k] += (w0[k] + w1[k]) + (w2[k] + w3[k]);
        }
        #pragma unroll
        for (int d = 0; d < 4; ++d) {
            float4 ev = eb[(size_t)d * PV + i];
            #pragma unroll
            for (int k = 0; k < KK; k++) {
                float a = s[k * 4 + d];
                a = fmaf(ev.x, w0[k], a);
                a = fmaf(ev.y, w1[k], a);
                a = fmaf(ev.z, w2[k], a);
                a = fmaf(ev.w, w3[k], a);
                s[k * 4 + d] = a;
            }
        }
    }

    // Block reduction: 8 warps x (20 sums + 5 counts)
    __shared__ float red[8][28];
    const int warp = threadIdx.x >> 5, lane = threadIdx.x & 31;
    #pragma unroll
    for (int v = 0; v < KK * 4; v++) {
        float r = warp_sum(s[v]);
        if (lane == 0) red[warp][v] = r;
    }
    #pragma unroll
    for (int k = 0; k < KK; k++) {
        float r = warp_sum(cnt[k]);
        if (lane == 0) red[warp][KK * 4 + k] = r;
    }
    __syncthreads();
    const int t = threadIdx.x;
    if (t < KK * 4) {
        float acc = 0.f;
        #pragma unroll
        for (int w = 0; w < 8; w++) acc += red[w][t];
        // s index: k = t>>2, local d = t&3 ; global d = z*4 + (t&3)
        atomicAdd(&g_sums[b * KK * DD + (t >> 2) * DD + z * 4 + (t & 3)], acc);
    } else if (t < KK * 4 + KK && z == 0) {
        float acc = 0.f;
        const int k = t - KK * 4;
        #pragma unroll
        for (int w = 0; w < 8; w++) acc += red[w][t];
        atomicAdd(&g_counts[b * KK + k], acc);
    }
}

// ---------------------------------------------------------------------------
// Kernel 2: per-pixel variance term. Each block derives centers + 1/count
// from g_sums/g_counts itself (no k_mid). Descending chunk order so the
// chunks pass1 touched last (still in L2) are read first.
// Accumulates val * (1/count[label]) -> single scalar per image.
// ---------------------------------------------------------------------------
__global__ void __launch_bounds__(TPB) k_pass2(const float4* __restrict__ emb,
                                               const int4* __restrict__ mask) {
    __shared__ float cs[48];   // [0,40) centers (k*8+d), [40,45) inv counts
    const int b = blockIdx.y;
    {
        const int t = threadIdx.x;
        if (t < 40) {
            float c = g_counts[b * KK + (t >> 3)];
            cs[t] = g_sums[b * KK * DD + t] * (1.f / fmaxf(c, 1.f));
        } else if (t < 45) {
            float c = g_counts[b * KK + (t - 40)];
            cs[t] = (c > 0.f) ? (1.f / c) : 0.f;
        }
    }
    __syncthreads();
    const float4* cs4 = (const float4*)cs;

    const float4* __restrict__ eb = emb + (size_t)b * DD * PV;
    const int4* __restrict__ mb = mask + (size_t)b * PV;

    float acc = 0.f;
    const int base = blockIdx.x * TPB + threadIdx.x;
    #pragma unroll 2
    for (int it = ITERS - 1; it >= 0; --it) {
        const int i = base + it * (CHUNKS * TPB);
        int4 mm = mb[i];
        const int k0 = min(max(mm.x - 1, 0), KK - 1) * 2;   // float4 index
        const int k1 = min(max(mm.y - 1, 0), KK - 1) * 2;
        const int k2 = min(max(mm.z - 1, 0), KK - 1) * 2;
        const int k3 = min(max(mm.w - 1, 0), KK - 1) * 2;

        float c0[4], c1[4], c2[4], c3[4];
        *(float4*)c0 = cs4[k0];
        *(float4*)c1 = cs4[k1];
        *(float4*)c2 = cs4[k2];
        *(float4*)c3 = cs4[k3];

        float a0 = 0.f, a1 = 0.f, a2 = 0.f, a3 = 0.f;
        #pragma unroll
        for (int d = 0; d < 4; ++d) {
            float4 ev = eb[(size_t)d * PV + i];
            float t0 = ev.x - c0[d]; a0 = fmaf(t0, t0, a0);
            float t1 = ev.y - c1[d]; a1 = fmaf(t1, t1, a1);
            float t2 = ev.z - c2[d]; a2 = fmaf(t2, t2, a2);
            float t3 = ev.w - c3[d]; a3 = fmaf(t3, t3, a3);
        }
        *(float4*)c0 = cs4[k0 + 1];
        *(float4*)c1 = cs4[k1 + 1];
        *(float4*)c2 = cs4[k2 + 1];
        *(float4*)c3 = cs4[k3 + 1];
        #pragma unroll
        for (int d = 4; d < 8; ++d) {
            float4 ev = eb[(size_t)d * PV + i];
            float t0 = ev.x - c0[d - 4]; a0 = fmaf(t0, t0, a0);
            float t1 = ev.y - c1[d - 4]; a1 = fmaf(t1, t1, a1);
            float t2 = ev.z - c2[d - 4]; a2 = fmaf(t2, t2, a2);
            float t3 = ev.w - c3[d - 4]; a3 = fmaf(t3, t3, a3);
        }

        // per-pixel weight: 1/count[label] if label>0 else 0
        float w0 = (mm.x > 0) ? cs[40 + (k0 >> 1)] : 0.f;
        float w1 = (mm.y > 0) ? cs[40 + (k1 >> 1)] : 0.f;
        float w2 = (mm.z > 0) ? cs[40 + (k2 >> 1)] : 0.f;
        float w3 = (mm.w > 0) ? cs[40 + (k3 >> 1)] : 0.f;

        float v0 = fmaxf(sqrtf(a0) - DELTA_V, 0.f);
        float v1 = fmaxf(sqrtf(a1) - DELTA_V, 0.f);
        float v2 = fmaxf(sqrtf(a2) - DELTA_V, 0.f);
        float v3 = fmaxf(sqrtf(a3) - DELTA_V, 0.f);
        acc = fmaf(v0 * v0, w0, acc);
        acc = fmaf(v1 * v1, w1, acc);
        acc = fmaf(v2 * v2, w2, acc);
        acc = fmaf(v3 * v3, w3, acc);
    }

    __shared__ float red[8];
    const int warp = threadIdx.x >> 5, lane = threadIdx.x & 31;
    float r = warp_sum(acc);
    if (lane == 0) red[warp] = r;
    __syncthreads();
    if (threadIdx.x == 0) {
        float s = 0.f;
        #pragma unroll
        for (int w = 0; w < 8; w++) s += red[w];
        atomicAdd(&g_var[b], s);
    }
}

// ---------------------------------------------------------------------------
// Kernel 3: finalize (centers, pairwise dist, reg, batch means)
// ---------------------------------------------------------------------------
__global__ void k_final(float* __restrict__ out, int out_size) {
    if (threadIdx.x != 0 || blockIdx.x != 0) return;
    float sv = 0.f, sd = 0.f, sr = 0.f, hs = 0.f;
    for (int b = 0; b < BB; b++) {
        float cnt[KK], pres[KK];
        float N = 0.f;
        #pragma unroll
        for (int k = 0; k < KK; k++) {
            cnt[k] = g_counts[b * KK + k];
            pres[k] = (cnt[k] > 0.f) ? 1.f : 0.f;
            N += pres[k];
        }
        float c[KK][DD];
        #pragma unroll
        for (int k = 0; k < KK; k++) {
            float inv = 1.f / fmaxf(cnt[k], 1.f);
            #pragma unroll
            for (int d = 0; d < DD; d++)
                c[k][d] = g_sums[b * KK * DD + k * DD + d] * inv;
        }
        // pairwise hinge
        float dist = 0.f;
        #pragma unroll
        for (int i = 0; i < KK; i++) {
            #pragma unroll
            for (int j = i + 1; j < KK; j++) {
                if (pres[i] > 0.f && pres[j] > 0.f) {
                    float dsq = 0.f;
                    #pragma unroll
                    for (int d = 0; d < DD; d++) {
                        float df = c[i][d] - c[j][d];
                        dsq = fmaf(df, df, dsq);
                    }
                    float term = fmaxf(2.f * DELTA_D - sqrtf(dsq), 0.f);
                    dist += term * term;
                }
            }
        }
        float npairs = N * (N - 1.f) * 0.5f;
        float dist_b = dist / ((N > 1.f) ? npairs : 1.f);

        float reg = 0.f;
        #pragma unroll
        for (int k = 0; k < KK; k++) {
            if (pres[k] > 0.f) {
                float nsq = 0.f;
                #pragma unroll
                for (int d = 0; d < DD; d++) nsq = fmaf(c[k][d], c[k][d], nsq);
                reg += sqrtf(nsq);
            }
        }
        float reg_b = reg / fmaxf(N, 1.f);
        float var_b = g_var[b] / fmaxf(N, 1.f);

        float has = (N > 0.f) ? 1.f : 0.f;
        sv += var_b * has;
        sd += dist_b * has;
        sr += reg_b * has;
        hs += has;
    }
    float den = fmaxf(hs, 1.f);
    sv /= den; sd /= den; sr /= den;
    float total = sv + sd + GAMMA_W * sr;
    float res[4] = {total, sv, sd, sr};
    for (int i = 0; i < 4 && i < out_size; i++) out[i] = res[i];
}

// ---------------------------------------------------------------------------
extern "C" void kernel_launch(void* const* d_in, const int* in_sizes, int n_in,
                              void* d_out, int out_size) {
    const float4* emb = (const float4*)d_in[0];
    const int4* mask = (const int4*)d_in[1];

    k_zero<<<1, 512>>>();
    dim3 g1(CHUNKS, BB, 2);
    k_pass1<<<g1, TPB>>>(emb, mask);
    dim3 g2(CHUNKS, BB);
    k_pass2<<<g2, TPB>>>(emb, mask);
    k_final<<<1, 32>>>((float*)d_out, out_size);
}

// round 7
// speedup vs baseline: 1.0922x; 1.0922x over previous
#include <cuda_runtime.h>

// Problem shape (fixed by dataset)
#define BB 8
#define DD 8
#define PP (512 * 1024)
#define PV (PP / 4)                 // 131072 float4/int4 quads per image
#define KK 5

#define TPB 256
#define NBLK 592                    // 4 blocks/SM x 148 SMs (GB300 has 152)
#define NTHREADS (NBLK * TPB)       // 151552
#define GBLK (NBLK / 2)             // 296 blocks per d-group
#define GTH (GBLK * TPB)            // 75776 threads per d-group

#define EMB_LINES (PV * 16 / 128 * DD)   // 16MB / 128B = 131072
#define MASK_LINES (PV * 16 / 128)       // 2MB  / 128B = 16384

#define DELTA_V 0.5f
#define DELTA_D 3.0f
#define GAMMA_W 0.001f

// Scratch (no allocations allowed -> __device__ globals)
__device__ float g_sums[BB * KK * DD];
__device__ float g_counts[BB * KK];
__device__ float g_var[BB];
__device__ unsigned int g_barc[16];

// ---------------------------------------------------------------------------
__global__ void k_zero() {
    int i = threadIdx.x;
    if (i < BB * KK * DD) g_sums[i] = 0.f;
    if (i < BB * KK) g_counts[i] = 0.f;
    if (i < BB) g_var[i] = 0.f;
    if (i < 16) g_barc[i] = 0u;
}

__device__ __forceinline__ float warp_sum(float v) {
    #pragma unroll
    for (int o = 16; o > 0; o >>= 1) v += __shfl_down_sync(0xffffffffu, v, o);
    return v;
}

// Grid-wide barrier: all NBLK blocks are guaranteed co-resident
// (__launch_bounds__(256,4) -> <=64 regs -> 4 blocks/SM -> 592 slots).
__device__ __forceinline__ void grid_bar(int idx) {
    __syncthreads();
    if (threadIdx.x == 0) {
        __threadfence();
        atomicAdd(&g_barc[idx], 1u);
        while (((volatile unsigned int*)g_barc)[idx] < (unsigned)NBLK) {
            __nanosleep(64);
        }
    }
    __syncthreads();
}

// ---------------------------------------------------------------------------
// Persistent kernel: for each image b: phase1 (segment sums) -> grid barrier
// -> phase2 (variance term from L2-resident image) + prefetch image b+1.
// Finalize in block 0 at the end.
// ---------------------------------------------------------------------------
__global__ void __launch_bounds__(TPB, 4) k_main(const float4* __restrict__ emb,
                                                 const int4* __restrict__ mask,
                                                 float* __restrict__ out,
                                                 int out_size) {
    __shared__ float red[8][28];
    __shared__ __align__(16) float cs[48];
    __shared__ float fs[BB * KK * DD];     // finalize staging (block 0 only)
    __shared__ float fc[BB * KK];
    __shared__ float fv[BB];
    __shared__ float pr[BB][4];

    const int tid = threadIdx.x;
    const int warp = tid >> 5, lane = tid & 31;
    const int g = blockIdx.x & 1;                       // d-plane group
    const int gtid = (blockIdx.x >> 1) * TPB + tid;     // id within group
    const int ptid = blockIdx.x * TPB + tid;            // id over all threads

    #pragma unroll 1
    for (int b = 0; b < BB; ++b) {
        // ================= phase 1: segment sums + counts =================
        {
            const float4* __restrict__ eb =
                emb + ((size_t)b * DD + (size_t)g * 4) * PV;
            const int4* __restrict__ mb = mask + (size_t)b * PV;

            float s[KK * 4];
            float cnt[KK];
            #pragma unroll
            for (int i = 0; i < KK * 4; i++) s[i] = 0.f;
            #pragma unroll
            for (int k = 0; k < KK; k++) cnt[k] = 0.f;

            #pragma unroll
            for (int it = 0; it < 2; ++it) {
                const int i = gtid + it * GTH;
                if (i < PV) {
                    int4 mm = mb[i];
                    float w0[KK], w1[KK], w2[KK], w3[KK];
                    #pragma unroll
                    for (int k = 0; k < KK; k++) {
                        w0[k] = (mm.x == k + 1) ? 1.f : 0.f;
                        w1[k] = (mm.y == k + 1) ? 1.f : 0.f;
                        w2[k] = (mm.z == k + 1) ? 1.f : 0.f;
                        w3[k] = (mm.w == k + 1) ? 1.f : 0.f;
                        cnt[k] += (w0[k] + w1[k]) + (w2[k] + w3[k]);
                    }
                    #pragma unroll
                    for (int d = 0; d < 4; ++d) {
                        float4 ev = eb[(size_t)d * PV + i];
                        #pragma unroll
                        for (int k = 0; k < KK; k++) {
                            float a = s[k * 4 + d];
                            a = fmaf(ev.x, w0[k], a);
                            a = fmaf(ev.y, w1[k], a);
                            a = fmaf(ev.z, w2[k], a);
                            a = fmaf(ev.w, w3[k], a);
                            s[k * 4 + d] = a;
                        }
                    }
                }
            }

            // Block reduction: 20 partial sums + 5 counts
            #pragma unroll
            for (int v = 0; v < KK * 4; v++) {
                float r = warp_sum(s[v]);
                if (lane == 0) red[warp][v] = r;
            }
            #pragma unroll
            for (int k = 0; k < KK; k++) {
                float r = warp_sum(cnt[k]);
                if (lane == 0) red[warp][KK * 4 + k] = r;
            }
            __syncthreads();
            if (tid < KK * 4) {
                float acc = 0.f;
                #pragma unroll
                for (int w = 0; w < 8; w++) acc += red[w][tid];
                atomicAdd(&g_sums[b * KK * DD + (tid >> 2) * DD + g * 4 + (tid & 3)], acc);
            } else if (tid < KK * 4 + KK && g == 0) {
                float acc = 0.f;
                #pragma unroll
                for (int w = 0; w < 8; w++) acc += red[w][tid];
                atomicAdd(&g_counts[b * KK + (tid - KK * 4)], acc);
            }
        }

        grid_bar(b);

        // ================= phase 2: variance term (image b in L2) =========
        {
            // Stage centers + inverse counts (bypass L1: lines may be stale)
            if (tid < 40) {
                float c = __ldcg(&g_counts[b * KK + (tid >> 3)]);
                cs[tid] = __ldcg(&g_sums[b * KK * DD + tid]) * (1.f / fmaxf(c, 1.f));
            } else if (tid < 45) {
                float c = __ldcg(&g_counts[b * KK + (tid - 40)]);
                cs[tid] = (c > 0.f) ? (1.f / c) : 0.f;
            }
            __syncthreads();

            // Prefetch next image into L2 so DRAM streams during this phase
            if (b + 1 < BB) {
                const char* pe = (const char*)(emb + (size_t)(b + 1) * DD * PV);
                const char* pm = (const char*)(mask + (size_t)(b + 1) * PV);
                if (ptid < EMB_LINES) {
                    asm volatile("prefetch.global.L2 [%0];" :: "l"(pe + (size_t)ptid * 128));
                } else if (ptid < EMB_LINES + MASK_LINES) {
                    asm volatile("prefetch.global.L2 [%0];"
                                 :: "l"(pm + (size_t)(ptid - EMB_LINES) * 128));
                }
            }

            float acc = 0.f;
            if (ptid < PV) {
                const float4* cs4 = (const float4*)cs;
                const float4* __restrict__ eb = emb + (size_t)b * DD * PV;
                const int4* __restrict__ mb = mask + (size_t)b * PV;
                const int i = ptid;
                int4 mm = mb[i];
                const int k0 = min(max(mm.x - 1, 0), KK - 1) * 2;
                const int k1 = min(max(mm.y - 1, 0), KK - 1) * 2;
                const int k2 = min(max(mm.z - 1, 0), KK - 1) * 2;
                const int k3 = min(max(mm.w - 1, 0), KK - 1) * 2;

                float c0[4], c1[4], c2[4], c3[4];
                *(float4*)c0 = cs4[k0];
                *(float4*)c1 = cs4[k1];
                *(float4*)c2 = cs4[k2];
                *(float4*)c3 = cs4[k3];

                float a0 = 0.f, a1 = 0.f, a2 = 0.f, a3 = 0.f;
                #pragma unroll
                for (int d = 0; d < 4; ++d) {
                    float4 ev = eb[(size_t)d * PV + i];
                    float t0 = ev.x - c0[d]; a0 = fmaf(t0, t0, a0);
                    float t1 = ev.y - c1[d]; a1 = fmaf(t1, t1, a1);
                    float t2 = ev.z - c2[d]; a2 = fmaf(t2, t2, a2);
                    float t3 = ev.w - c3[d]; a3 = fmaf(t3, t3, a3);
                }
                *(float4*)c0 = cs4[k0 + 1];
                *(float4*)c1 = cs4[k1 + 1];
                *(float4*)c2 = cs4[k2 + 1];
                *(float4*)c3 = cs4[k3 + 1];
                #pragma unroll
                for (int d = 4; d < 8; ++d) {
                    float4 ev = eb[(size_t)d * PV + i];
                    float t0 = ev.x - c0[d - 4]; a0 = fmaf(t0, t0, a0);
                    float t1 = ev.y - c1[d - 4]; a1 = fmaf(t1, t1, a1);
                    float t2 = ev.z - c2[d - 4]; a2 = fmaf(t2, t2, a2);
                    float t3 = ev.w - c3[d - 4]; a3 = fmaf(t3, t3, a3);
                }

                float w0 = (mm.x > 0) ? cs[40 + (k0 >> 1)] : 0.f;
                float w1 = (mm.y > 0) ? cs[40 + (k1 >> 1)] : 0.f;
                float w2 = (mm.z > 0) ? cs[40 + (k2 >> 1)] : 0.f;
                float w3 = (mm.w > 0) ? cs[40 + (k3 >> 1)] : 0.f;

                float v0 = fmaxf(sqrtf(a0) - DELTA_V, 0.f);
                float v1 = fmaxf(sqrtf(a1) - DELTA_V, 0.f);
                float v2 = fmaxf(sqrtf(a2) - DELTA_V, 0.f);
                float v3 = fmaxf(sqrtf(a3) - DELTA_V, 0.f);
                acc = fmaf(v0 * v0, w0, acc);
                acc = fmaf(v1 * v1, w1, acc);
                acc = fmaf(v2 * v2, w2, acc);
                acc = fmaf(v3 * v3, w3, acc);
            }

            __syncthreads();   // red[] reuse
            float r = warp_sum(acc);
            if (lane == 0) red[warp][0] = r;
            __syncthreads();
            if (tid == 0) {
                float s = 0.f;
                #pragma unroll
                for (int w = 0; w < 8; w++) s += red[w][0];
                atomicAdd(&g_var[b], s);
            }
        }
    }

    grid_bar(BB);

    // ===================== finalize (block 0 only) ========================
    if (blockIdx.x == 0) {
        for (int i = tid; i < BB * KK * DD; i += TPB) fs[i] = __ldcg(&g_sums[i]);
        if (tid < BB * KK) fc[tid] = __ldcg(&g_counts[tid]);
        if (tid < BB) fv[tid] = __ldcg(&g_var[tid]);
        __syncthreads();

        if (tid < BB) {
            const int b = tid;
            float cnt[KK], pres[KK];
            float N = 0.f;
            #pragma unroll
            for (int k = 0; k < KK; k++) {
                cnt[k] = fc[b * KK + k];
                pres[k] = (cnt[k] > 0.f) ? 1.f : 0.f;
                N += pres[k];
            }
            float c[KK][DD];
            #pragma unroll
            for (int k = 0; k < KK; k++) {
                float inv = 1.f / fmaxf(cnt[k], 1.f);
                #pragma unroll
                for (int d = 0; d < DD; d++)
                    c[k][d] = fs[b * KK * DD + k * DD + d] * inv;
            }
            float dist = 0.f;
            #pragma unroll
            for (int i = 0; i < KK; i++) {
                #pragma unroll
                for (int j = i + 1; j < KK; j++) {
                    if (pres[i] > 0.f && pres[j] > 0.f) {
                        float dsq = 0.f;
                        #pragma unroll
                        for (int d = 0; d < DD; d++) {
                            float df = c[i][d] - c[j][d];
                            dsq = fmaf(df, df, dsq);
                        }
                        float term = fmaxf(2.f * DELTA_D - sqrtf(dsq), 0.f);
                        dist += term * term;
                    }
                }
            }
            float npairs = N * (N - 1.f) * 0.5f;
            float reg = 0.f;
            #pragma unroll
            for (int k = 0; k < KK; k++) {
                if (pres[k] > 0.f) {
                    float nsq = 0.f;
                    #pragma unroll
                    for (int d = 0; d < DD; d++) nsq = fmaf(c[k][d], c[k][d], nsq);
                    reg += sqrtf(nsq);
                }
            }
            pr[b][0] = fv[b] / fmaxf(N, 1.f);                    // var_b
            pr[b][1] = dist / ((N > 1.f) ? npairs : 1.f);        // dist_b
            pr[b][2] = reg / fmaxf(N, 1.f);                      // reg_b
            pr[b][3] = (N > 0.f) ? 1.f : 0.f;                    // has
        }
        __syncthreads();

        if (tid == 0) {
            float sv = 0.f, sd = 0.f, sr = 0.f, hs = 0.f;
            #pragma unroll
            for (int b = 0; b < BB; b++) {
                sv += pr[b][0] * pr[b][3];
                sd += pr[b][1] * pr[b][3];
                sr += pr[b][2] * pr[b][3];
                hs += pr[b][3];
            }
            float den = fmaxf(hs, 1.f);
            sv /= den; sd /= den; sr /= den;
            float total = sv + sd + GAMMA_W * sr;
            float res[4] = {total, sv, sd, sr};
            for (int i = 0; i < 4 && i < out_size; i++) out[i] = res[i];
        }
    }
}

// ---------------------------------------------------------------------------
extern "C" void kernel_launch(void* const* d_in, const int* in_sizes, int n_in,
                              void* d_out, int out_size) {
    const float4* emb = (const float4*)d_in[0];
    const int4* mask = (const int4*)d_in[1];

    k_zero<<<1, 512>>>();
    k_main<<<NBLK, TPB>>>(emb, mask, (float*)d_out, out_size);
}

// round 9
// speedup vs baseline: 1.4995x; 1.3729x over previous
#include <cuda_runtime.h>

// Problem shape (fixed by dataset)
#define BB 8
#define DD 8
#define PP (512 * 1024)
#define PV (PP / 4)                  // 131072 float4/int4 quads per image
#define KK 5

#define TPB 256
#define P1CH 37                      // pass1: 37*8*2 = 592 blocks (4/SM x 148)
#define P1TH (P1CH * TPB)            // 9472 threads per (b,z) group
#define P2CH 74                      // pass2: 74*8 = 592 blocks
#define P2TH (P2CH * TPB)            // 18944 threads per image

#define DELTA_V 0.5f
#define DELTA_D 3.0f
#define GAMMA_W 0.001f

// Scratch (no allocations allowed -> __device__ globals)
__device__ float g_sums[BB * KK * DD];
__device__ float g_counts[BB * KK];
__device__ float g_var[BB];

// ---------------------------------------------------------------------------
__global__ void k_zero() {
    int i = threadIdx.x;
    if (i < BB * KK * DD) g_sums[i] = 0.f;
    if (i < BB * KK) g_counts[i] = 0.f;
    if (i < BB) g_var[i] = 0.f;
}

__device__ __forceinline__ float warp_sum(float v) {
    #pragma unroll
    for (int o = 16; o > 0; o >>= 1) v += __shfl_down_sync(0xffffffffu, v, o);
    return v;
}

// ---------------------------------------------------------------------------
// Pass 1: segment sums + counts. d-split via blockIdx.z (4 planes each) to
// keep accumulators at 20 -> <=64 regs -> 4 blocks/SM.
// grid (37, 8, 2), block 256.
// ---------------------------------------------------------------------------
__global__ void __launch_bounds__(TPB, 4) k_pass1(const float4* __restrict__ emb,
                                                  const int4* __restrict__ mask) {
    const int b = blockIdx.y;
    const int z = blockIdx.z;                    // planes [4z, 4z+4)
    const float4* __restrict__ eb = emb + ((size_t)b * DD + (size_t)z * 4) * PV;
    const int4* __restrict__ mb = mask + (size_t)b * PV;

    float s[KK * 4];
    float cnt[KK];
    #pragma unroll
    for (int i = 0; i < KK * 4; i++) s[i] = 0.f;
    #pragma unroll
    for (int k = 0; k < KK; k++) cnt[k] = 0.f;

    for (int i = blockIdx.x * TPB + threadIdx.x; i < PV; i += P1TH) {
        int4 mm = mb[i];
        float w0[KK], w1[KK], w2[KK], w3[KK];
        #pragma unroll
        for (int k = 0; k < KK; k++) {
            w0[k] = (mm.x == k + 1) ? 1.f : 0.f;
            w1[k] = (mm.y == k + 1) ? 1.f : 0.f;
            w2[k] = (mm.z == k + 1) ? 1.f : 0.f;
            w3[k] = (mm.w == k + 1) ? 1.f : 0.f;
            cnt[k] += (w0[k] + w1[k]) + (w2[k] + w3[k]);
        }
        #pragma unroll
        for (int d = 0; d < 4; ++d) {
            float4 ev = eb[(size_t)d * PV + i];
            #pragma unroll
            for (int k = 0; k < KK; k++) {
                float a = s[k * 4 + d];
                a = fmaf(ev.x, w0[k], a);
                a = fmaf(ev.y, w1[k], a);
                a = fmaf(ev.z, w2[k], a);
                a = fmaf(ev.w, w3[k], a);
                s[k * 4 + d] = a;
            }
        }
    }

    // Block reduction: 20 sums + 5 counts
    __shared__ float red[8][28];
    const int warp = threadIdx.x >> 5, lane = threadIdx.x & 31;
    #pragma unroll
    for (int v = 0; v < KK * 4; v++) {
        float r = warp_sum(s[v]);
        if (lane == 0) red[warp][v] = r;
    }
    #pragma unroll
    for (int k = 0; k < KK; k++) {
        float r = warp_sum(cnt[k]);
        if (lane == 0) red[warp][KK * 4 + k] = r;
    }
    __syncthreads();
    const int t = threadIdx.x;
    if (t < KK * 4) {
        float acc = 0.f;
        #pragma unroll
        for (int w = 0; w < 8; w++) acc += red[w][t];
        atomicAdd(&g_sums[b * KK * DD + (t >> 2) * DD + z * 4 + (t & 3)], acc);
    } else if (t < KK * 4 + KK && z == 0) {
        float acc = 0.f;
        #pragma unroll
        for (int w = 0; w < 8; w++) acc += red[w][t];
        atomicAdd(&g_counts[b * KK + (t - KK * 4)], acc);
    }
}

// ---------------------------------------------------------------------------
// Pass 2: per-pixel variance term. One image per blockIdx.y (static b ->
// scalar accumulator, no dynamic register indexing). Centers + inv counts
// derived from g_sums/g_counts per block. grid (74, 8), block 256.
// acc += val * (1/count[label]).
// ---------------------------------------------------------------------------
__global__ void __launch_bounds__(TPB, 4) k_pass2(const float4* __restrict__ emb,
                                                  const int4* __restrict__ mask) {
    __shared__ __align__(16) float cs[48];   // [0,40) centers k*8+d, [40,45) inv
    const int b = blockIdx.y;
    {
        const int t = threadIdx.x;
        if (t < 40) {
            float c = g_counts[b * KK + (t >> 3)];
            cs[t] = g_sums[b * KK * DD + t] * (1.f / fmaxf(c, 1.f));
        } else if (t < 45) {
            float c = g_counts[b * KK + (t - 40)];
            cs[t] = (c > 0.f) ? (1.f / c) : 0.f;
        }
    }
    __syncthreads();
    const float4* cs4 = (const float4*)cs;

    const float4* __restrict__ eb = emb + (size_t)b * DD * PV;
    const int4* __restrict__ mb = mask + (size_t)b * PV;

    float acc = 0.f;
    for (int i = blockIdx.x * TPB + threadIdx.x; i < PV; i += P2TH) {
        int4 mm = mb[i];
        const int k0 = min(max(mm.x - 1, 0), KK - 1) * 2;   // float4 index
        const int k1 = min(max(mm.y - 1, 0), KK - 1) * 2;
        const int k2 = min(max(mm.z - 1, 0), KK - 1) * 2;
        const int k3 = min(max(mm.w - 1, 0), KK - 1) * 2;

        float c0[4], c1[4], c2[4], c3[4];
        *(float4*)c0 = cs4[k0];
        *(float4*)c1 = cs4[k1];
        *(float4*)c2 = cs4[k2];
        *(float4*)c3 = cs4[k3];

        float a0 = 0.f, a1 = 0.f, a2 = 0.f, a3 = 0.f;
        #pragma unroll
        for (int d = 0; d < 4; ++d) {
            float4 ev = eb[(size_t)d * PV + i];
            float t0 = ev.x - c0[d]; a0 = fmaf(t0, t0, a0);
            float t1 = ev.y - c1[d]; a1 = fmaf(t1, t1, a1);
            float t2 = ev.z - c2[d]; a2 = fmaf(t2, t2, a2);
            float t3 = ev.w - c3[d]; a3 = fmaf(t3, t3, a3);
        }
        *(float4*)c0 = cs4[k0 + 1];
        *(float4*)c1 = cs4[k1 + 1];
        *(float4*)c2 = cs4[k2 + 1];
        *(float4*)c3 = cs4[k3 + 1];
        #pragma unroll
        for (int d = 4; d < 8; ++d) {
            float4 ev = eb[(size_t)d * PV + i];
            float t0 = ev.x - c0[d - 4]; a0 = fmaf(t0, t0, a0);
            float t1 = ev.y - c1[d - 4]; a1 = fmaf(t1, t1, a1);
            float t2 = ev.z - c2[d - 4]; a2 = fmaf(t2, t2, a2);
            float t3 = ev.w - c3[d - 4]; a3 = fmaf(t3, t3, a3);
        }

        float w0 = (mm.x > 0) ? cs[40 + (k0 >> 1)] : 0.f;
        float w1 = (mm.y > 0) ? cs[40 + (k1 >> 1)] : 0.f;
        float w2 = (mm.z > 0) ? cs[40 + (k2 >> 1)] : 0.f;
        float w3 = (mm.w > 0) ? cs[40 + (k3 >> 1)] : 0.f;

        float v0 = fmaxf(sqrtf(a0) - DELTA_V, 0.f);
        float v1 = fmaxf(sqrtf(a1) - DELTA_V, 0.f);
        float v2 = fmaxf(sqrtf(a2) - DELTA_V, 0.f);
        float v3 = fmaxf(sqrtf(a3) - DELTA_V, 0.f);
        acc += fmaf(v0 * v0, w0, v1 * v1 * w1) + fmaf(v2 * v2, w2, v3 * v3 * w3);
    }

    __shared__ float red[8];
    const int warp = threadIdx.x >> 5, lane = threadIdx.x & 31;
    float r = warp_sum(acc);
    if (lane == 0) red[warp] = r;
    __syncthreads();
    if (threadIdx.x == 0) {
        float s = 0.f;
        #pragma unroll
        for (int w = 0; w < 8; w++) s += red[w];
        atomicAdd(&g_var[b], s);
    }
}

// ---------------------------------------------------------------------------
// Finalize: parallel-staged loads, 8 threads compute per-image terms.
// ---------------------------------------------------------------------------
__global__ void k_final(float* __restrict__ out, int out_size) {
    __shared__ float fs[BB * KK * DD];
    __shared__ float fc[BB * KK];
    __shared__ float fv[BB];
    __shared__ float pr[BB][4];
    const int tid = threadIdx.x;

    for (int i = tid; i < BB * KK * DD; i += 256) fs[i] = g_sums[i];
    if (tid < BB * KK) fc[tid] = g_counts[tid];
    if (tid < BB) fv[tid] = g_var[tid];
    __syncthreads();

    if (tid < BB) {
        const int b = tid;
        float cnt[KK], pres[KK];
        float N = 0.f;
        #pragma unroll
        for (int k = 0; k < KK; k++) {
            cnt[k] = fc[b * KK + k];
            pres[k] = (cnt[k] > 0.f) ? 1.f : 0.f;
            N += pres[k];
        }
        float c[KK][DD];
        #pragma unroll
        for (int k = 0; k < KK; k++) {
            float inv = 1.f / fmaxf(cnt[k], 1.f);
            #pragma unroll
            for (int d = 0; d < DD; d++)
                c[k][d] = fs[b * KK * DD + k * DD + d] * inv;
        }
        float dist = 0.f;
        #pragma unroll
        for (int i = 0; i < KK; i++) {
            #pragma unroll
            for (int j = i + 1; j < KK; j++) {
                if (pres[i] > 0.f && pres[j] > 0.f) {
                    float dsq = 0.f;
                    #pragma unroll
                    for (int d = 0; d < DD; d++) {
                        float df = c[i][d] - c[j][d];
                        dsq = fmaf(df, df, dsq);
                    }
                    float term = fmaxf(2.f * DELTA_D - sqrtf(dsq), 0.f);
                    dist += term * term;
                }
            }
        }
        float npairs = N * (N - 1.f) * 0.5f;
        float reg = 0.f;
        #pragma unroll
        for (int k = 0; k < KK; k++) {
            if (pres[k] > 0.f) {
                float nsq = 0.f;
                #pragma unroll
                for (int d = 0; d < DD; d++) nsq = fmaf(c[k][d], c[k][d], nsq);
                reg += sqrtf(nsq);
            }
        }
        pr[b][0] = fv[b] / fmaxf(N, 1.f);
        pr[b][1] = dist / ((N > 1.f) ? npairs : 1.f);
        pr[b][2] = reg / fmaxf(N, 1.f);
        pr[b][3] = (N > 0.f) ? 1.f : 0.f;
    }
    __syncthreads();

    if (tid == 0) {
        float sv = 0.f, sd = 0.f, sr = 0.f, hs = 0.f;
        #pragma unroll
        for (int b = 0; b < BB; b++) {
            sv += pr[b][0] * pr[b][3];
            sd += pr[b][1] * pr[b][3];
            sr += pr[b][2] * pr[b][3];
            hs += pr[b][3];
        }
        float den = fmaxf(hs, 1.f);
        sv /= den; sd /= den; sr /= den;
        float total = sv + sd + GAMMA_W * sr;
        float res[4] = {total, sv, sd, sr};
        for (int i = 0; i < 4 && i < out_size; i++) out[i] = res[i];
    }
}

// ---------------------------------------------------------------------------
extern "C" void kernel_launch(void* const* d_in, const int* in_sizes, int n_in,
                              void* d_out, int out_size) {
    const float4* emb = (const float4*)d_in[0];
    const int4* mask = (const int4*)d_in[1];

    k_zero<<<1, 512>>>();
    dim3 g1(P1CH, BB, 2);
    k_pass1<<<g1, TPB>>>(emb, mask);
    dim3 g2(P2CH, BB);
    k_pass2<<<g2, TPB>>>(emb, mask);
    k_final<<<1, 256>>>((float*)d_out, out_size);
}